// round 15
// baseline (speedup 1.0000x reference)
#include <cuda_runtime.h>
#include <cstdint>

// Problem constants
#define N_PRE       20000
#define VEC_DIM     300
#define INPUT_SIZE  10000
#define HIDDEN      256
#define OUT_DIM     556
#define N_TOKENS    4096

#define TOK_PER_BLK 8
#define GRID        (N_TOKENS / TOK_PER_BLK)   // 512
#define TPB         256
#define VEC_BYTES   (VEC_DIM * 4)              // 1200, multiple of 16
#define SLOT_FLOATS 304                         // 1216 B slot (16B-aligned stride)

__device__ __forceinline__ uint32_t smem_u32(const void* p) {
    uint32_t a;
    asm("{ .reg .u64 t; cvta.to.shared.u64 t, %1; cvt.u32.u64 %0, t; }"
        : "=r"(a) : "l"(p));
    return a;
}

// One block = 8 tokens.
//  Warp 0 : orchestrates the vector rows through the ASYNC-PROXY path:
//           cp.async.bulk G->S (vectors row) / zero-fill smem for t>=N_PRE,
//           mbarrier wait, cp.async.bulk S->G (out row). 2 bulk ops per token
//           replace ~19 LSU wavefronts per token.
//  All warps (incl. 0): hidden gather, h = tid:
//           out[tok][300+h] = b[h] + (t>=N_PRE ? W[h*10000 + t-N_PRE] : 0)
// No __syncthreads: each warp redundantly loads the 8 token ids (one 32B line).
__global__ __launch_bounds__(TPB)
void encoder_bulk(const int* __restrict__ batch,
                  const float* __restrict__ vectors,
                  const float* __restrict__ W,
                  const float* __restrict__ b,
                  float* __restrict__ out)
{
    __shared__ __align__(16) float slots[TOK_PER_BLK][SLOT_FLOATS];
    __shared__ __align__(8)  unsigned long long mbar;

    const int tid  = threadIdx.x;
    const int lane = tid & 31;
    const int warp = tid >> 5;
    const int tok0 = blockIdx.x * TOK_PER_BLK;

    // Every warp loads the 8 token ids itself (coalesced 32B, L2 broadcast).
    int t_own = 0;
    if (lane < TOK_PER_BLK)
        t_own = batch[tok0 + lane];

    const float bias = b[tid];   // independent; overlaps everything

    // ------------------- warp 0: async-proxy vector pipeline -------------------
    if (warp == 0) {
        const uint32_t mb = smem_u32(&mbar);
        if (lane == 0)
            asm volatile("mbarrier.init.shared.b64 [%0], 1;" :: "r"(mb) : "memory");

        // Zero-fill slots whose token has no pretrained vector (warp-converged).
#pragma unroll
        for (int j = 0; j < TOK_PER_BLK; j++) {
            const int tj = __shfl_sync(0xffffffffu, t_own, j);
            if (tj >= N_PRE) {
                float4* s4 = reinterpret_cast<float4*>(slots[j]);
                for (int k = lane; k < VEC_DIM / 4; k += 32)
                    s4[k] = make_float4(0.f, 0.f, 0.f, 0.f);
            }
        }
        __syncwarp();
        // Order generic STS zeros + mbarrier init before async-proxy ops.
        asm volatile("fence.proxy.async.shared::cta;" ::: "memory");

        // expect_tx = total bytes the bulk loads will deliver (may be 0).
        const unsigned m  = __ballot_sync(0xffffffffu,
                                          (lane < TOK_PER_BLK) && (t_own < N_PRE));
        const unsigned bytes = __popc(m) * (unsigned)VEC_BYTES;
        if (lane == 0)
            asm volatile("mbarrier.arrive.expect_tx.shared.b64 _, [%0], %1;"
                         :: "r"(mb), "r"(bytes) : "memory");
        __syncwarp();

        // Bulk loads: one 1200B copy per pretrained token, lane j owns token j.
        if (lane < TOK_PER_BLK && t_own < N_PRE) {
            const uint32_t dst = smem_u32(slots[lane]);
            const float*   src = vectors + (size_t)t_own * VEC_DIM;
            asm volatile(
                "cp.async.bulk.shared::cluster.global.mbarrier::complete_tx::bytes "
                "[%0], [%1], %2, [%3];"
                :: "r"(dst), "l"(src), "r"((unsigned)VEC_BYTES), "r"(mb)
                : "memory");
        }
    }

    // ------------------- all warps: hidden gather (LSU path) -------------------
    float w[TOK_PER_BLK];
#pragma unroll
    for (int j = 0; j < TOK_PER_BLK; j++) {
        const int tj = __shfl_sync(0xffffffffu, t_own, j);
        w[j] = (tj >= N_PRE) ? W[(size_t)tid * INPUT_SIZE + (tj - N_PRE)] : 0.f;
    }
#pragma unroll
    for (int j = 0; j < TOK_PER_BLK; j++)
        out[(size_t)(tok0 + j) * OUT_DIM + VEC_DIM + tid] = bias + w[j];

    // ------------------- warp 0: drain vector rows to out -------------------
    if (warp == 0) {
        const uint32_t mb = smem_u32(&mbar);
        // Wait parity 0 (single-phase use per launch).
        asm volatile(
            "{\n\t"
            ".reg .pred P;\n\t"
            "WL_%=:\n\t"
            "mbarrier.try_wait.parity.shared.b64 P, [%0], 0, 0x989680;\n\t"
            "@P bra WD_%=;\n\t"
            "bra WL_%=;\n\t"
            "WD_%=:\n\t"
            "}"
            :: "r"(mb) : "memory");

        if (lane < TOK_PER_BLK) {
            const uint32_t src = smem_u32(slots[lane]);
            float* dst = out + (size_t)(tok0 + lane) * OUT_DIM;   // 2224B-aligned
            asm volatile(
                "cp.async.bulk.global.shared::cta.bulk_group [%0], [%1], %2;"
                :: "l"(dst), "r"(src), "r"((unsigned)VEC_BYTES)
                : "memory");
            asm volatile("cp.async.bulk.commit_group;" ::: "memory");
            asm volatile("cp.async.bulk.wait_group.read 0;" ::: "memory");
        }
    }
}

extern "C" void kernel_launch(void* const* d_in, const int* in_sizes, int n_in,
                              void* d_out, int out_size)
{
    const int*   batch   = (const int*)  d_in[0];
    const float* vectors = (const float*)d_in[1];
    const float* W       = (const float*)d_in[2];
    const float* b       = (const float*)d_in[3];
    float*       out     = (float*)d_out;

    encoder_bulk<<<GRID, TPB>>>(batch, vectors, W, b, out);
}